// round 1
// baseline (speedup 1.0000x reference)
#include <cuda_runtime.h>

#define B_  4
#define C_  128
#define N_  4096
#define CO_ 128

// Scratch (device globals — no allocation allowed)
__device__ float g_Q [B_ * C_ * N_];
__device__ float g_K [B_ * C_ * N_];
__device__ float g_V [B_ * C_ * N_];
__device__ float g_SA[B_ * C_ * N_];

// ---------------------------------------------------------------------------
// proj: dst[b,o,n] = sum_c W[o,c] * src[b,c,n] + bias[o]
// grid (N/64, B), 256 threads. Output tile 128(o) x 64(n), thread = 4o x 8n.
// ---------------------------------------------------------------------------
__global__ __launch_bounds__(256) void proj_kernel(
    const float* __restrict__ src, const float* __restrict__ W,
    const float* __restrict__ bias, float* __restrict__ dst)
{
    __shared__ float Wt[32][132];   // [k][o], padded
    __shared__ float xs[32][64];    // [k][n]

    const int t    = threadIdx.x;
    const int nblk = blockIdx.x;
    const int b    = blockIdx.y;
    const int n0   = 8 * (t & 7);
    const int o0   = 4 * (t >> 3);

    float acc[4][8];
#pragma unroll
    for (int i = 0; i < 4; i++)
#pragma unroll
        for (int j = 0; j < 8; j++) acc[i][j] = 0.f;

    const float* srcB = src + (size_t)b * C_ * N_ + (size_t)nblk * 64;

    for (int k0 = 0; k0 < C_; k0 += 32) {
        // load W chunk transposed: Wt[k][o]
        for (int v = t; v < 1024; v += 256) {
            int o = v >> 3, q = v & 7;
            float4 w = *(const float4*)(W + (size_t)o * C_ + k0 + 4 * q);
            Wt[4 * q + 0][o] = w.x;
            Wt[4 * q + 1][o] = w.y;
            Wt[4 * q + 2][o] = w.z;
            Wt[4 * q + 3][o] = w.w;
        }
        // load x chunk: xs[k][n]
        for (int v = t; v < 512; v += 256) {
            int k = v >> 4, q = (v & 15) * 4;
            *(float4*)&xs[k][q] = *(const float4*)(srcB + (size_t)(k0 + k) * N_ + q);
        }
        __syncthreads();

#pragma unroll
        for (int k = 0; k < 32; k++) {
            float4 w  = *(float4*)&Wt[k][o0];
            float4 xa = *(float4*)&xs[k][n0];
            float4 xb = *(float4*)&xs[k][n0 + 4];
            float wv[4] = {w.x, w.y, w.z, w.w};
            float xv[8] = {xa.x, xa.y, xa.z, xa.w, xb.x, xb.y, xb.z, xb.w};
#pragma unroll
            for (int i = 0; i < 4; i++)
#pragma unroll
                for (int j = 0; j < 8; j++)
                    acc[i][j] = fmaf(wv[i], xv[j], acc[i][j]);
        }
        __syncthreads();
    }

#pragma unroll
    for (int i = 0; i < 4; i++) {
        float bv = bias[o0 + i];
        float* drow = dst + ((size_t)b * 128 + (o0 + i)) * N_ + (size_t)nblk * 64 + n0;
        float4 r0 = make_float4(acc[i][0] + bv, acc[i][1] + bv, acc[i][2] + bv, acc[i][3] + bv);
        float4 r1 = make_float4(acc[i][4] + bv, acc[i][5] + bv, acc[i][6] + bv, acc[i][7] + bv);
        *(float4*)(drow)     = r0;
        *(float4*)(drow + 4) = r1;
    }
}

// ---------------------------------------------------------------------------
// Fused flash attention (fp32): per (query-tile of 64, batch).
// Writes g_SA = gamma * softmax(Q^T K) applied to V  + x
// ---------------------------------------------------------------------------
// shared memory layout (floats)
#define SM_QS   0                       // [128][64]  Q tile (c-major)
#define SM_KS   (SM_QS + 128 * 64)      // [128][64]  K tile
#define SM_VT   (SM_KS + 128 * 64)      // [64][132]  V tile transposed [j][c]
#define SM_PT   (SM_VT + 64 * 132)      // [64][68]   P transposed [j][i]
#define SM_PART (SM_PT + 64 * 68)       // [64][17]   row partials
#define SM_M    (SM_PART + 64 * 17)
#define SM_L    (SM_M + 64)
#define SM_SC   (SM_L + 64)
#define SM_TOT  (SM_SC + 64)
#define SMEM_BYTES (SM_TOT * 4)

extern __shared__ float sm[];

__global__ __launch_bounds__(256) void attn_kernel(
    const float* __restrict__ x, const float* __restrict__ gamma)
{
    float* Qs    = sm + SM_QS;
    float* Ks    = sm + SM_KS;
    float* Vt    = sm + SM_VT;
    float* Pt    = sm + SM_PT;
    float* part  = sm + SM_PART;
    float* m_sm  = sm + SM_M;
    float* l_sm  = sm + SM_L;
    float* sc_sm = sm + SM_SC;

    const int t    = threadIdx.x;
    const int qblk = blockIdx.x;
    const int b    = blockIdx.y;
    const int N0   = qblk * 64;

    const int ti = t & 15;        // score i-group / O i-group
    const int tj = t >> 4;        // score j-group / O c-group
    const int i0 = 4 * ti;
    const int j0 = 4 * tj;
    const int c0 = 8 * tj;

    const float* Qg = g_Q + (size_t)b * C_ * N_ + N0;
    const float* Kg = g_K + (size_t)b * C_ * N_;
    const float* Vg = g_V + (size_t)b * C_ * N_;

    // load Q tile: Qs[c][i]
    for (int v = t; v < 2048; v += 256) {
        int c = v >> 4, q = (v & 15) * 4;
        *(float4*)&Qs[c * 64 + q] = *(const float4*)(Qg + (size_t)c * N_ + q);
    }
    if (t < 64) { m_sm[t] = -1e30f; l_sm[t] = 0.f; }

    float oacc[4][8];
#pragma unroll
    for (int i = 0; i < 4; i++)
#pragma unroll
        for (int j = 0; j < 8; j++) oacc[i][j] = 0.f;

    __syncthreads();

    for (int kt = 0; kt < N_ / 64; kt++) {
        const int nk = kt * 64;
        // load K tile (c-major) and V tile (transposed [j][c])
        for (int v = t; v < 2048; v += 256) {
            int c = v >> 4, q = (v & 15) * 4;
            *(float4*)&Ks[c * 64 + q] = *(const float4*)(Kg + (size_t)c * N_ + nk + q);
            float4 vv = *(const float4*)(Vg + (size_t)c * N_ + nk + q);
            Vt[(q + 0) * 132 + c] = vv.x;
            Vt[(q + 1) * 132 + c] = vv.y;
            Vt[(q + 2) * 132 + c] = vv.z;
            Vt[(q + 3) * 132 + c] = vv.w;
        }
        __syncthreads();

        // scores: s[ii][jj] = sum_c Q[c][i0+ii] * K[c][j0+jj]
        float s[4][4];
#pragma unroll
        for (int i = 0; i < 4; i++)
#pragma unroll
            for (int j = 0; j < 4; j++) s[i][j] = 0.f;

#pragma unroll 4
        for (int c = 0; c < C_; c++) {
            float4 qv = *(float4*)&Qs[c * 64 + i0];
            float4 kv = *(float4*)&Ks[c * 64 + j0];
            float qa[4] = {qv.x, qv.y, qv.z, qv.w};
            float ka[4] = {kv.x, kv.y, kv.z, kv.w};
#pragma unroll
            for (int i = 0; i < 4; i++)
#pragma unroll
                for (int j = 0; j < 4; j++)
                    s[i][j] = fmaf(qa[i], ka[j], s[i][j]);
        }

        // partial row max
#pragma unroll
        for (int i = 0; i < 4; i++) {
            float pm = fmaxf(fmaxf(s[i][0], s[i][1]), fmaxf(s[i][2], s[i][3]));
            part[(i0 + i) * 17 + tj] = pm;
        }
        __syncthreads();
        if (t < 64) {
            float mx = part[t * 17];
#pragma unroll
            for (int q = 1; q < 16; q++) mx = fmaxf(mx, part[t * 17 + q]);
            float mold = m_sm[t];
            float mnew = fmaxf(mold, mx);
            m_sm[t]  = mnew;
            sc_sm[t] = __expf(mold - mnew);
        }
        __syncthreads();

        // exponentiate; write P transposed; partial row sums
        float p[4][4];
#pragma unroll
        for (int i = 0; i < 4; i++) {
            float mrow = m_sm[i0 + i];
#pragma unroll
            for (int j = 0; j < 4; j++) p[i][j] = __expf(s[i][j] - mrow);
        }
#pragma unroll
        for (int j = 0; j < 4; j++) {
            *(float4*)&Pt[(j0 + j) * 68 + i0] =
                make_float4(p[0][j], p[1][j], p[2][j], p[3][j]);
        }
#pragma unroll
        for (int i = 0; i < 4; i++)
            part[(i0 + i) * 17 + tj] = p[i][0] + p[i][1] + p[i][2] + p[i][3];
        __syncthreads();

        if (t < 64) {
            float ssum = 0.f;
#pragma unroll
            for (int q = 0; q < 16; q++) ssum += part[t * 17 + q];
            l_sm[t] = l_sm[t] * sc_sm[t] + ssum;
        }

        // rescale accumulators and accumulate P^T * V^T
#pragma unroll
        for (int i = 0; i < 4; i++) {
            float scl = sc_sm[i0 + i];
#pragma unroll
            for (int cc = 0; cc < 8; cc++) oacc[i][cc] *= scl;
        }
#pragma unroll 4
        for (int j = 0; j < 64; j++) {
            float4 pv = *(float4*)&Pt[j * 68 + i0];
            float4 va = *(float4*)&Vt[j * 132 + c0];
            float4 vb = *(float4*)&Vt[j * 132 + c0 + 4];
            float pa[4] = {pv.x, pv.y, pv.z, pv.w};
            float vv[8] = {va.x, va.y, va.z, va.w, vb.x, vb.y, vb.z, vb.w};
#pragma unroll
            for (int i = 0; i < 4; i++)
#pragma unroll
                for (int cc = 0; cc < 8; cc++)
                    oacc[i][cc] = fmaf(pa[i], vv[cc], oacc[i][cc]);
        }
        __syncthreads();
    }

    // normalize, stage into Qs[c][i] for coalesced writeback
#pragma unroll
    for (int i = 0; i < 4; i++) {
        float inv = 1.f / l_sm[i0 + i];
#pragma unroll
        for (int cc = 0; cc < 8; cc++)
            Qs[(c0 + cc) * 64 + (i0 + i)] = oacc[i][cc] * inv;
    }
    __syncthreads();

    const float g = gamma[0];
    const float* xB  = x    + (size_t)b * C_ * N_ + N0;
    float*       saB = g_SA + (size_t)b * C_ * N_ + N0;
    for (int v = t; v < 2048; v += 256) {
        int c = v >> 4, q = (v & 15) * 4;
        float4 o  = *(float4*)&Qs[c * 64 + q];
        float4 xv = *(const float4*)(xB + (size_t)c * N_ + q);
        float4 r = make_float4(g * o.x + xv.x, g * o.y + xv.y,
                               g * o.z + xv.z, g * o.w + xv.w);
        *(float4*)(saB + (size_t)c * N_ + q) = r;
    }
}

// ---------------------------------------------------------------------------
extern "C" void kernel_launch(void* const* d_in, const int* in_sizes, int n_in,
                              void* d_out, int out_size)
{
    const float* x     = (const float*)d_in[0];
    const float* Wq    = (const float*)d_in[1];
    const float* bq    = (const float*)d_in[2];
    const float* Wk    = (const float*)d_in[3];
    const float* bk    = (const float*)d_in[4];
    const float* Wv    = (const float*)d_in[5];
    const float* bv    = (const float*)d_in[6];
    const float* gamma = (const float*)d_in[7];
    const float* Wo    = (const float*)d_in[8];
    const float* bo    = (const float*)d_in[9];
    float* out = (float*)d_out;

    float *Qp, *Kp, *Vp, *SAp;
    cudaGetSymbolAddress((void**)&Qp,  g_Q);
    cudaGetSymbolAddress((void**)&Kp,  g_K);
    cudaGetSymbolAddress((void**)&Vp,  g_V);
    cudaGetSymbolAddress((void**)&SAp, g_SA);

    cudaFuncSetAttribute(attn_kernel,
                         cudaFuncAttributeMaxDynamicSharedMemorySize, SMEM_BYTES);

    dim3 grid(N_ / 64, B_);
    dim3 blk(256);

    proj_kernel<<<grid, blk>>>(x, Wq, bq, Qp);
    proj_kernel<<<grid, blk>>>(x, Wk, bk, Kp);
    proj_kernel<<<grid, blk>>>(x, Wv, bv, Vp);
    attn_kernel<<<grid, blk, SMEM_BYTES>>>(x, gamma);
    proj_kernel<<<grid, blk>>>(SAp, Wo, bo, out);
}

// round 2
// speedup vs baseline: 2.2162x; 2.2162x over previous
#include <cuda_runtime.h>
#include <cstdint>

#define B_  4
#define C_  128
#define N_  4096
#define CO_ 128

// Scratch (device globals — no allocation allowed)
__device__ float g_Q [B_ * C_ * N_];
__device__ float g_K [B_ * C_ * N_];
__device__ float g_V [B_ * C_ * N_];
__device__ float g_SA[B_ * C_ * N_];

// ---------------------------------------------------------------------------
// helpers
// ---------------------------------------------------------------------------
__device__ __forceinline__ uint32_t f2tf32(float x) {
    uint32_t r;
    asm("cvt.rna.tf32.f32 %0, %1;" : "=r"(r) : "f"(x));
    return r;
}

__device__ __forceinline__ void mma_tf32(float* c, const uint32_t* a,
                                         uint32_t b0, uint32_t b1) {
    asm volatile(
        "mma.sync.aligned.m16n8k8.row.col.f32.tf32.tf32.f32 "
        "{%0,%1,%2,%3}, {%4,%5,%6,%7}, {%8,%9}, {%0,%1,%2,%3};"
        : "+f"(c[0]), "+f"(c[1]), "+f"(c[2]), "+f"(c[3])
        : "r"(a[0]), "r"(a[1]), "r"(a[2]), "r"(a[3]), "r"(b0), "r"(b1));
}

// ---------------------------------------------------------------------------
// proj: dst[b,o,n] = sum_c W[o,c] * src[b,c,n] + bias[o]   (fp32, unchanged)
// ---------------------------------------------------------------------------
__global__ __launch_bounds__(256) void proj_kernel(
    const float* __restrict__ src, const float* __restrict__ W,
    const float* __restrict__ bias, float* __restrict__ dst)
{
    __shared__ float Wt[32][132];
    __shared__ float xs[32][64];

    const int t    = threadIdx.x;
    const int nblk = blockIdx.x;
    const int b    = blockIdx.y;
    const int n0   = 8 * (t & 7);
    const int o0   = 4 * (t >> 3);

    float acc[4][8];
#pragma unroll
    for (int i = 0; i < 4; i++)
#pragma unroll
        for (int j = 0; j < 8; j++) acc[i][j] = 0.f;

    const float* srcB = src + (size_t)b * C_ * N_ + (size_t)nblk * 64;

    for (int k0 = 0; k0 < C_; k0 += 32) {
        for (int v = t; v < 1024; v += 256) {
            int o = v >> 3, q = v & 7;
            float4 w = *(const float4*)(W + (size_t)o * C_ + k0 + 4 * q);
            Wt[4 * q + 0][o] = w.x;
            Wt[4 * q + 1][o] = w.y;
            Wt[4 * q + 2][o] = w.z;
            Wt[4 * q + 3][o] = w.w;
        }
        for (int v = t; v < 512; v += 256) {
            int k = v >> 4, q = (v & 15) * 4;
            *(float4*)&xs[k][q] = *(const float4*)(srcB + (size_t)(k0 + k) * N_ + q);
        }
        __syncthreads();

#pragma unroll
        for (int k = 0; k < 32; k++) {
            float4 w  = *(float4*)&Wt[k][o0];
            float4 xa = *(float4*)&xs[k][n0];
            float4 xb = *(float4*)&xs[k][n0 + 4];
            float wv[4] = {w.x, w.y, w.z, w.w};
            float xv[8] = {xa.x, xa.y, xa.z, xa.w, xb.x, xb.y, xb.z, xb.w};
#pragma unroll
            for (int i = 0; i < 4; i++)
#pragma unroll
                for (int j = 0; j < 8; j++)
                    acc[i][j] = fmaf(wv[i], xv[j], acc[i][j]);
        }
        __syncthreads();
    }

#pragma unroll
    for (int i = 0; i < 4; i++) {
        float bv = bias[o0 + i];
        float* drow = dst + ((size_t)b * 128 + (o0 + i)) * N_ + (size_t)nblk * 64 + n0;
        *(float4*)(drow)     = make_float4(acc[i][0] + bv, acc[i][1] + bv, acc[i][2] + bv, acc[i][3] + bv);
        *(float4*)(drow + 4) = make_float4(acc[i][4] + bv, acc[i][5] + bv, acc[i][6] + bv, acc[i][7] + bv);
    }
}

// ---------------------------------------------------------------------------
// attn: tf32 mma flash attention.
// Block = 128 threads (4 warps). Q tile = 64 queries (16 per warp).
// K tile = 32 keys per iteration. 3-MMA hi/lo split for QK^T, tf32 PV.
// ---------------------------------------------------------------------------
// smem layout (in floats)
#define OFF_QPH 0                       // [4w][16kc][32lane][4reg] tf32 bits (8192)
#define OFF_QPL (OFF_QPH + 8192)        // same, lo part                  (8192)
#define OFF_KS  (OFF_QPL + 8192)        // K fp32 [128c][40]              (5120)
#define OFF_VS  (OFF_KS + 5120)         // V tf32 bits [128c][36]         (4608)
#define OFF_PS  (OFF_VS + 4608)         // P tf32 bits [64i][36]          (2304)
#define SM_FLOATS (OFF_PS + 2304)       // 28416 floats = 113664 B
#define OFF_OS  OFF_KS                  // O staging [128c][68] (reuse, 8704)
#define ATTN_SMEM_BYTES (SM_FLOATS * 4)

#define NKT (N_ / 32)                   // 128 key tiles

__global__ __launch_bounds__(128) void attn_kernel(
    const float* __restrict__ x, const float* __restrict__ gamma)
{
    extern __shared__ float smf[];
    uint32_t* QPH = (uint32_t*)(smf + OFF_QPH);
    uint32_t* QPL = (uint32_t*)(smf + OFF_QPL);
    float*    KSf = smf + OFF_KS;
    uint32_t* VSu = (uint32_t*)(smf + OFF_VS);
    uint32_t* PSu = (uint32_t*)(smf + OFF_PS);
    float*    OSf = smf + OFF_OS;

    const int t    = threadIdx.x;
    const int w    = t >> 5;            // warp 0..3
    const int lane = t & 31;
    const int g2   = lane >> 2;         // group id 0..7
    const int tid  = lane & 3;          // thread-in-group
    const int qblk = blockIdx.x;
    const int b    = blockIdx.y;
    const int N0   = qblk * 64;

    const float* Qg = g_Q + (size_t)b * C_ * N_ + N0;
    const float* Kg = g_K + (size_t)b * C_ * N_;
    const float* Vg = g_V + (size_t)b * C_ * N_;

    // ---- load Q tile, split hi/lo, store frag-packed (once) ----
    for (int v = t; v < 64 * 128; v += 128) {
        int i = v & 63, c = v >> 6;
        float q = Qg[(size_t)c * N_ + i];
        uint32_t hi = f2tf32(q);
        uint32_t lo = f2tf32(q - __uint_as_float(hi));
        int wq = i >> 4, gq = i & 7, s = (i >> 3) & 1;
        int l  = (gq << 2) | (c & 3);
        int r  = s | (((c >> 2) & 1) << 1);
        int idx = ((wq * 16 + (c >> 3)) * 32 + l) * 4 + r;
        QPH[idx] = hi;
        QPL[idx] = lo;
    }

    // ---- state ----
    float oacc[16][4];
#pragma unroll
    for (int nf = 0; nf < 16; nf++)
#pragma unroll
        for (int r = 0; r < 4; r++) oacc[nf][r] = 0.f;
    float m0 = -1e30f, m1 = -1e30f, l0 = 0.f, l1 = 0.f;

    // ---- prefetch first K/V tile into registers ----
    float4 kpre[8], vpre[8];
#pragma unroll
    for (int r = 0; r < 8; r++) {
        int v = t + 128 * r;
        int c = v >> 3, j = (v & 7) * 4;
        kpre[r] = *(const float4*)(Kg + (size_t)c * N_ + j);
        vpre[r] = *(const float4*)(Vg + (size_t)c * N_ + j);
    }

    for (int kt = 0; kt < NKT; kt++) {
        __syncthreads();   // previous iter's smem reads done

        // store tiles into smem
#pragma unroll
        for (int r = 0; r < 8; r++) {
            int v = t + 128 * r;
            int c = v >> 3, j = (v & 7) * 4;
            *(float4*)&KSf[c * 40 + j] = kpre[r];
            float4 vv = vpre[r];
            uint4 vb;
            vb.x = f2tf32(vv.x); vb.y = f2tf32(vv.y);
            vb.z = f2tf32(vv.z); vb.w = f2tf32(vv.w);
            *(uint4*)&VSu[c * 36 + j] = vb;
        }
        __syncthreads();

        // prefetch next tile
        if (kt + 1 < NKT) {
            int nk2 = (kt + 1) * 32;
#pragma unroll
            for (int r = 0; r < 8; r++) {
                int v = t + 128 * r;
                int c = v >> 3, j = (v & 7) * 4;
                kpre[r] = *(const float4*)(Kg + (size_t)c * N_ + nk2 + j);
                vpre[r] = *(const float4*)(Vg + (size_t)c * N_ + nk2 + j);
            }
        }

        // ---- S = Q^T K  (split tf32: 3 mma per frag) ----
        float sacc[4][4];
#pragma unroll
        for (int jf = 0; jf < 4; jf++)
#pragma unroll
            for (int r = 0; r < 4; r++) sacc[jf][r] = 0.f;

#pragma unroll
        for (int kc = 0; kc < 16; kc++) {
            const uint32_t* ah = &QPH[((w * 16 + kc) * 32 + lane) * 4];
            const uint32_t* al = &QPL[((w * 16 + kc) * 32 + lane) * 4];
            uint4 ahv = *(const uint4*)ah;
            uint4 alv = *(const uint4*)al;
            uint32_t ahr[4] = {ahv.x, ahv.y, ahv.z, ahv.w};
            uint32_t alr[4] = {alv.x, alv.y, alv.z, alv.w};
#pragma unroll
            for (int jf = 0; jf < 4; jf++) {
                float b0f = KSf[(8 * kc + tid) * 40 + 8 * jf + g2];
                float b1f = KSf[(8 * kc + tid + 4) * 40 + 8 * jf + g2];
                uint32_t bh0 = f2tf32(b0f);
                uint32_t bh1 = f2tf32(b1f);
                uint32_t bl0 = f2tf32(b0f - __uint_as_float(bh0));
                uint32_t bl1 = f2tf32(b1f - __uint_as_float(bh1));
                mma_tf32(sacc[jf], ahr, bh0, bh1);
                mma_tf32(sacc[jf], alr, bh0, bh1);
                mma_tf32(sacc[jf], ahr, bl0, bl1);
            }
        }

        // ---- online softmax ----
        float mx0 = fmaxf(fmaxf(sacc[0][0], sacc[0][1]), fmaxf(sacc[1][0], sacc[1][1]));
        mx0 = fmaxf(mx0, fmaxf(fmaxf(sacc[2][0], sacc[2][1]), fmaxf(sacc[3][0], sacc[3][1])));
        float mx1 = fmaxf(fmaxf(sacc[0][2], sacc[0][3]), fmaxf(sacc[1][2], sacc[1][3]));
        mx1 = fmaxf(mx1, fmaxf(fmaxf(sacc[2][2], sacc[2][3]), fmaxf(sacc[3][2], sacc[3][3])));
        mx0 = fmaxf(mx0, __shfl_xor_sync(0xffffffffu, mx0, 1));
        mx0 = fmaxf(mx0, __shfl_xor_sync(0xffffffffu, mx0, 2));
        mx1 = fmaxf(mx1, __shfl_xor_sync(0xffffffffu, mx1, 1));
        mx1 = fmaxf(mx1, __shfl_xor_sync(0xffffffffu, mx1, 2));

        float mn0 = fmaxf(m0, mx0), mn1 = fmaxf(m1, mx1);
        float sc0 = __expf(m0 - mn0), sc1 = __expf(m1 - mn1);
        m0 = mn0; m1 = mn1;

        float rs0 = 0.f, rs1 = 0.f;
        const int r0 = 16 * w + g2;
#pragma unroll
        for (int jf = 0; jf < 4; jf++) {
            float p00 = __expf(sacc[jf][0] - m0);
            float p01 = __expf(sacc[jf][1] - m0);
            float p10 = __expf(sacc[jf][2] - m1);
            float p11 = __expf(sacc[jf][3] - m1);
            rs0 += p00 + p01;
            rs1 += p10 + p11;
            int cbase = 8 * jf + 2 * tid;
            PSu[r0 * 36 + cbase]           = f2tf32(p00);
            PSu[r0 * 36 + cbase + 1]       = f2tf32(p01);
            PSu[(r0 + 8) * 36 + cbase]     = f2tf32(p10);
            PSu[(r0 + 8) * 36 + cbase + 1] = f2tf32(p11);
        }
        rs0 += __shfl_xor_sync(0xffffffffu, rs0, 1);
        rs0 += __shfl_xor_sync(0xffffffffu, rs0, 2);
        rs1 += __shfl_xor_sync(0xffffffffu, rs1, 1);
        rs1 += __shfl_xor_sync(0xffffffffu, rs1, 2);
        l0 = l0 * sc0 + rs0;
        l1 = l1 * sc1 + rs1;

        // rescale O accumulators
#pragma unroll
        for (int nf = 0; nf < 16; nf++) {
            oacc[nf][0] *= sc0; oacc[nf][1] *= sc0;
            oacc[nf][2] *= sc1; oacc[nf][3] *= sc1;
        }
        __syncwarp();

        // ---- O += P V^T (tf32) ----
#pragma unroll
        for (int kc = 0; kc < 4; kc++) {
            uint32_t pa[4];
            pa[0] = PSu[r0 * 36 + 8 * kc + tid];
            pa[1] = PSu[(r0 + 8) * 36 + 8 * kc + tid];
            pa[2] = PSu[r0 * 36 + 8 * kc + tid + 4];
            pa[3] = PSu[(r0 + 8) * 36 + 8 * kc + tid + 4];
#pragma unroll
            for (int nf = 0; nf < 16; nf++) {
                uint32_t b0 = VSu[(8 * nf + g2) * 36 + 8 * kc + tid];
                uint32_t b1 = VSu[(8 * nf + g2) * 36 + 8 * kc + tid + 4];
                mma_tf32(oacc[nf], pa, b0, b1);
            }
        }
    }

    // ---- normalize, stage O to smem (overwrites K/V region) ----
    __syncthreads();
    {
        float inv0 = 1.f / l0, inv1 = 1.f / l1;
        const int i_ = 16 * w + g2;
#pragma unroll
        for (int nf = 0; nf < 16; nf++) {
            int c = 8 * nf + 2 * tid;
            OSf[c * 68 + i_]           = oacc[nf][0] * inv0;
            OSf[(c + 1) * 68 + i_]     = oacc[nf][1] * inv0;
            OSf[c * 68 + i_ + 8]       = oacc[nf][2] * inv1;
            OSf[(c + 1) * 68 + i_ + 8] = oacc[nf][3] * inv1;
        }
    }
    __syncthreads();

    // ---- residual + gamma, coalesced writeback ----
    const float gm = gamma[0];
    const float* xB  = x    + (size_t)b * C_ * N_ + N0;
    float*       saB = g_SA + (size_t)b * C_ * N_ + N0;
    for (int v = t; v < 2048; v += 128) {
        int c = v >> 4, q = (v & 15) * 4;
        float4 o  = *(float4*)&OSf[c * 68 + q];
        float4 xv = *(const float4*)(xB + (size_t)c * N_ + q);
        float4 rr = make_float4(gm * o.x + xv.x, gm * o.y + xv.y,
                                gm * o.z + xv.z, gm * o.w + xv.w);
        *(float4*)(saB + (size_t)c * N_ + q) = rr;
    }
}

// ---------------------------------------------------------------------------
extern "C" void kernel_launch(void* const* d_in, const int* in_sizes, int n_in,
                              void* d_out, int out_size)
{
    const float* x     = (const float*)d_in[0];
    const float* Wq    = (const float*)d_in[1];
    const float* bq    = (const float*)d_in[2];
    const float* Wk    = (const float*)d_in[3];
    const float* bk    = (const float*)d_in[4];
    const float* Wv    = (const float*)d_in[5];
    const float* bv    = (const float*)d_in[6];
    const float* gamma = (const float*)d_in[7];
    const float* Wo    = (const float*)d_in[8];
    const float* bo    = (const float*)d_in[9];
    float* out = (float*)d_out;

    float *Qp, *Kp, *Vp, *SAp;
    cudaGetSymbolAddress((void**)&Qp,  g_Q);
    cudaGetSymbolAddress((void**)&Kp,  g_K);
    cudaGetSymbolAddress((void**)&Vp,  g_V);
    cudaGetSymbolAddress((void**)&SAp, g_SA);

    cudaFuncSetAttribute(attn_kernel,
                         cudaFuncAttributeMaxDynamicSharedMemorySize, ATTN_SMEM_BYTES);

    dim3 pgrid(N_ / 64, B_);
    proj_kernel<<<pgrid, 256>>>(x, Wq, bq, Qp);
    proj_kernel<<<pgrid, 256>>>(x, Wk, bk, Kp);
    proj_kernel<<<pgrid, 256>>>(x, Wv, bv, Vp);

    dim3 agrid(N_ / 64, B_);
    attn_kernel<<<agrid, 128, ATTN_SMEM_BYTES>>>(x, gamma);

    proj_kernel<<<pgrid, 256>>>(SAp, Wo, bo, out);
}

// round 3
// speedup vs baseline: 3.5286x; 1.5922x over previous
#include <cuda_runtime.h>
#include <cuda_bf16.h>
#include <cstdint>

#define B_  4
#define C_  128
#define N_  4096
#define CO_ 128

// -------- scratch device globals --------
__device__ uint32_t g_Qh[B_ * 4096 * 64];          // [b][i][cp] bf16x2 hi
__device__ uint32_t g_Ql[B_ * 4096 * 64];          // lo
__device__ uint32_t g_K2[B_ * 128 * 5120];         // [b][kt][ hi:64x40 | lo:64x40 ]
__device__ uint32_t g_V2[B_ * 128 * 4096];         // [b][c][n] tf32 bits
__device__ float    g_SA[B_ * C_ * N_];

// -------- helpers --------
__device__ __forceinline__ uint32_t f2tf32(float x) {
    uint32_t r;
    asm("cvt.rna.tf32.f32 %0, %1;" : "=r"(r) : "f"(x));
    return r;
}
__device__ __forceinline__ void bf16_split(float x, uint16_t& h, uint16_t& l) {
    __nv_bfloat16 hb = __float2bfloat16_rn(x);
    float hf = __bfloat162float(hb);
    __nv_bfloat16 lb = __float2bfloat16_rn(x - hf);
    h = __bfloat16_as_ushort(hb);
    l = __bfloat16_as_ushort(lb);
}
__device__ __forceinline__ uint32_t pack16(uint16_t lo, uint16_t hi) {
    return (uint32_t)lo | ((uint32_t)hi << 16);
}
__device__ __forceinline__ void mma_tf32(float* c, const uint32_t* a,
                                         uint32_t b0, uint32_t b1) {
    asm volatile(
        "mma.sync.aligned.m16n8k8.row.col.f32.tf32.tf32.f32 "
        "{%0,%1,%2,%3}, {%4,%5,%6,%7}, {%8,%9}, {%0,%1,%2,%3};"
        : "+f"(c[0]), "+f"(c[1]), "+f"(c[2]), "+f"(c[3])
        : "r"(a[0]), "r"(a[1]), "r"(a[2]), "r"(a[3]), "r"(b0), "r"(b1));
}
__device__ __forceinline__ void mma_bf16(float* c, const uint32_t* a,
                                         uint32_t b0, uint32_t b1) {
    asm volatile(
        "mma.sync.aligned.m16n8k16.row.col.f32.bf16.bf16.f32 "
        "{%0,%1,%2,%3}, {%4,%5,%6,%7}, {%8,%9}, {%0,%1,%2,%3};"
        : "+f"(c[0]), "+f"(c[1]), "+f"(c[2]), "+f"(c[3])
        : "r"(a[0]), "r"(a[1]), "r"(a[2]), "r"(a[3]), "r"(b0), "r"(b1));
}
__device__ __forceinline__ void cp_async16(uint32_t dst, const void* src) {
    asm volatile("cp.async.cg.shared.global [%0], [%1], 16;" :: "r"(dst), "l"(src));
}
__device__ __forceinline__ void cp_async8(uint32_t dst, const void* src) {
    asm volatile("cp.async.ca.shared.global [%0], [%1], 8;" :: "r"(dst), "l"(src));
}
__device__ __forceinline__ void cp_commit() { asm volatile("cp.async.commit_group;"); }
__device__ __forceinline__ void cp_wait1()  { asm volatile("cp.async.wait_group 1;"); }

// ---------------------------------------------------------------------------
// Merged QKV projection. Emits Q/K bf16-split packed, V tf32.
// grid (64, B), 256 threads.
// ---------------------------------------------------------------------------
#define QKV_SMEM_BYTES ((3 * 32 * 132 + 32 * 64) * 4)

__global__ __launch_bounds__(256) void qkv_proj_kernel(
    const float* __restrict__ x,
    const float* __restrict__ Wq, const float* __restrict__ bq,
    const float* __restrict__ Wk, const float* __restrict__ bk,
    const float* __restrict__ Wv, const float* __restrict__ bv)
{
    extern __shared__ float psm[];
    float* Wt = psm;                    // [3][32][132]
    float* xs = psm + 3 * 32 * 132;     // [32][64]

    const int t = threadIdx.x, nblk = blockIdx.x, b = blockIdx.y;
    const int n0 = 8 * (t & 7), o0 = 4 * (t >> 3);

    float aq[4][8], ak[4][8], av[4][8];
#pragma unroll
    for (int i = 0; i < 4; i++)
#pragma unroll
        for (int j = 0; j < 8; j++) { aq[i][j] = 0.f; ak[i][j] = 0.f; av[i][j] = 0.f; }

    const float* srcB = x + (size_t)b * C_ * N_ + (size_t)nblk * 64;
    const float* Ws[3] = {Wq, Wk, Wv};

    for (int k0 = 0; k0 < C_; k0 += 32) {
        for (int v = t; v < 1024; v += 256) {
            int o = v >> 3, q = v & 7;
#pragma unroll
            for (int s3 = 0; s3 < 3; s3++) {
                float4 w = *(const float4*)(Ws[s3] + (size_t)o * C_ + k0 + 4 * q);
                float* W_ = Wt + s3 * 4224;
                W_[(4 * q + 0) * 132 + o] = w.x;
                W_[(4 * q + 1) * 132 + o] = w.y;
                W_[(4 * q + 2) * 132 + o] = w.z;
                W_[(4 * q + 3) * 132 + o] = w.w;
            }
        }
        for (int v = t; v < 512; v += 256) {
            int k = v >> 4, q = (v & 15) * 4;
            *(float4*)&xs[k * 64 + q] = *(const float4*)(srcB + (size_t)(k0 + k) * N_ + q);
        }
        __syncthreads();

#pragma unroll
        for (int k = 0; k < 32; k++) {
            float4 xa = *(float4*)&xs[k * 64 + n0];
            float4 xb = *(float4*)&xs[k * 64 + n0 + 4];
            float xv[8] = {xa.x, xa.y, xa.z, xa.w, xb.x, xb.y, xb.z, xb.w};
            float4 wq4 = *(float4*)&Wt[0 * 4224 + k * 132 + o0];
            float4 wk4 = *(float4*)&Wt[1 * 4224 + k * 132 + o0];
            float4 wv4 = *(float4*)&Wt[2 * 4224 + k * 132 + o0];
            float wqv[4] = {wq4.x, wq4.y, wq4.z, wq4.w};
            float wkv[4] = {wk4.x, wk4.y, wk4.z, wk4.w};
            float wvv[4] = {wv4.x, wv4.y, wv4.z, wv4.w};
#pragma unroll
            for (int i = 0; i < 4; i++)
#pragma unroll
                for (int j = 0; j < 8; j++) {
                    aq[i][j] = fmaf(wqv[i], xv[j], aq[i][j]);
                    ak[i][j] = fmaf(wkv[i], xv[j], ak[i][j]);
                    av[i][j] = fmaf(wvv[i], xv[j], av[i][j]);
                }
        }
        __syncthreads();
    }

    // ---- epilogue ----
    const float bq0 = bq[o0], bq1 = bq[o0 + 1], bq2 = bq[o0 + 2], bq3 = bq[o0 + 3];
    const float bk0 = bk[o0], bk1 = bk[o0 + 1], bk2 = bk[o0 + 2], bk3 = bk[o0 + 3];
    const int crow = o0 >> 1;

#pragma unroll
    for (int jj = 0; jj < 8; jj++) {
        int n = nblk * 64 + n0 + jj;
        // Q
        uint16_t h0, l0, h1, l1, h2, l2, h3, l3;
        bf16_split(aq[0][jj] + bq0, h0, l0);
        bf16_split(aq[1][jj] + bq1, h1, l1);
        bf16_split(aq[2][jj] + bq2, h2, l2);
        bf16_split(aq[3][jj] + bq3, h3, l3);
        size_t qb = ((size_t)b * 4096 + n) * 64 + crow;
        g_Qh[qb]     = pack16(h0, h1);
        g_Qh[qb + 1] = pack16(h2, h3);
        g_Ql[qb]     = pack16(l0, l1);
        g_Ql[qb + 1] = pack16(l2, l3);
        // K
        bf16_split(ak[0][jj] + bk0, h0, l0);
        bf16_split(ak[1][jj] + bk1, h1, l1);
        bf16_split(ak[2][jj] + bk2, h2, l2);
        bf16_split(ak[3][jj] + bk3, h3, l3);
        int kt = n >> 5, jin = n & 31;
        size_t kb = ((size_t)b * 128 + kt) * 5120;
        g_K2[kb + crow * 40 + jin]              = pack16(h0, h1);
        g_K2[kb + (crow + 1) * 40 + jin]        = pack16(h2, h3);
        g_K2[kb + 2560 + crow * 40 + jin]       = pack16(l0, l1);
        g_K2[kb + 2560 + (crow + 1) * 40 + jin] = pack16(l2, l3);
    }
    // V (tf32, [c][n])
#pragma unroll
    for (int i = 0; i < 4; i++) {
        float bvv = bv[o0 + i];
        uint32_t vv[8];
#pragma unroll
        for (int jj = 0; jj < 8; jj++) vv[jj] = f2tf32(av[i][jj] + bvv);
        size_t vb = ((size_t)b * 128 + o0 + i) * 4096 + nblk * 64 + n0;
        *(uint4*)&g_V2[vb]     = make_uint4(vv[0], vv[1], vv[2], vv[3]);
        *(uint4*)&g_V2[vb + 4] = make_uint4(vv[4], vv[5], vv[6], vv[7]);
    }
}

// ---------------------------------------------------------------------------
// out-proj (fp32, as round 2)
// ---------------------------------------------------------------------------
__global__ __launch_bounds__(256) void proj_kernel(
    const float* __restrict__ src, const float* __restrict__ W,
    const float* __restrict__ bias, float* __restrict__ dst)
{
    __shared__ float Wt[32][132];
    __shared__ float xs[32][64];

    const int t = threadIdx.x, nblk = blockIdx.x, b = blockIdx.y;
    const int n0 = 8 * (t & 7), o0 = 4 * (t >> 3);

    float acc[4][8];
#pragma unroll
    for (int i = 0; i < 4; i++)
#pragma unroll
        for (int j = 0; j < 8; j++) acc[i][j] = 0.f;

    const float* srcB = src + (size_t)b * C_ * N_ + (size_t)nblk * 64;

    for (int k0 = 0; k0 < C_; k0 += 32) {
        for (int v = t; v < 1024; v += 256) {
            int o = v >> 3, q = v & 7;
            float4 w = *(const float4*)(W + (size_t)o * C_ + k0 + 4 * q);
            Wt[4 * q + 0][o] = w.x;
            Wt[4 * q + 1][o] = w.y;
            Wt[4 * q + 2][o] = w.z;
            Wt[4 * q + 3][o] = w.w;
        }
        for (int v = t; v < 512; v += 256) {
            int k = v >> 4, q = (v & 15) * 4;
            *(float4*)&xs[k][q] = *(const float4*)(srcB + (size_t)(k0 + k) * N_ + q);
        }
        __syncthreads();

#pragma unroll
        for (int k = 0; k < 32; k++) {
            float4 w  = *(float4*)&Wt[k][o0];
            float4 xa = *(float4*)&xs[k][n0];
            float4 xb = *(float4*)&xs[k][n0 + 4];
            float wv[4] = {w.x, w.y, w.z, w.w};
            float xv[8] = {xa.x, xa.y, xa.z, xa.w, xb.x, xb.y, xb.z, xb.w};
#pragma unroll
            for (int i = 0; i < 4; i++)
#pragma unroll
                for (int j = 0; j < 8; j++)
                    acc[i][j] = fmaf(wv[i], xv[j], acc[i][j]);
        }
        __syncthreads();
    }

#pragma unroll
    for (int i = 0; i < 4; i++) {
        float bv = bias[o0 + i];
        float* drow = dst + ((size_t)b * 128 + (o0 + i)) * N_ + (size_t)nblk * 64 + n0;
        *(float4*)(drow)     = make_float4(acc[i][0] + bv, acc[i][1] + bv, acc[i][2] + bv, acc[i][3] + bv);
        *(float4*)(drow + 4) = make_float4(acc[i][4] + bv, acc[i][5] + bv, acc[i][6] + bv, acc[i][7] + bv);
    }
}

// ---------------------------------------------------------------------------
// attn: bf16-split QK^T (registers A) + tf32 PV, cp.async double buffered.
// Block = 128 threads (4 warps), 64-query tile, 32-key tiles.
// ---------------------------------------------------------------------------
#define NKT 128
// smem (uints)
#define OFF_K 0                     // [2][5120]  (hi 64x40 | lo 64x40)
#define OFF_V 10240                 // [2][128*36]
#define OFF_P 19456                 // [64][36]
#define SM_UINTS 21760
#define ATTN_SMEM_BYTES (SM_UINTS * 4)

__global__ __launch_bounds__(128) void attn_kernel(
    const float* __restrict__ x, const float* __restrict__ gamma)
{
    extern __shared__ uint32_t smu[];
    uint32_t* Ps = smu + OFF_P;

    const int t = threadIdx.x;
    const int w = t >> 5, lane = t & 31;
    const int g2 = lane >> 2, tid = lane & 3;
    const int qblk = blockIdx.x, b = blockIdx.y;
    const int N0 = qblk * 64;
    const int I0 = N0 + 16 * w;

    const uint32_t sbase = (uint32_t)__cvta_generic_to_shared(smu);

    // ---- Q A-fragments into registers ----
    uint32_t qh[8][4], ql[8][4];
    {
        const uint32_t* Qhg = g_Qh + ((size_t)b * 4096 + I0) * 64;
        const uint32_t* Qlg = g_Ql + ((size_t)b * 4096 + I0) * 64;
        const int r0c = g2 * 64, r8c = (g2 + 8) * 64;
#pragma unroll
        for (int kc = 0; kc < 8; kc++) {
            int cl = 8 * kc + tid;
            qh[kc][0] = Qhg[r0c + cl];     qh[kc][1] = Qhg[r8c + cl];
            qh[kc][2] = Qhg[r0c + cl + 4]; qh[kc][3] = Qhg[r8c + cl + 4];
            ql[kc][0] = Qlg[r0c + cl];     ql[kc][1] = Qlg[r8c + cl];
            ql[kc][2] = Qlg[r0c + cl + 4]; ql[kc][3] = Qlg[r8c + cl + 4];
        }
    }

    const uint32_t* Kg = g_K2 + (size_t)b * 128 * 5120;
    const uint32_t* Vg = g_V2 + (size_t)b * 128 * 4096;

    // cp.async issue for stage s, tile kt
    auto issue = [&](int s, int kt) {
#pragma unroll
        for (int r = 0; r < 10; r++) {
            int idx = t + 128 * r;
            cp_async16(sbase + (OFF_K + s * 5120 + idx * 4) * 4,
                       Kg + (size_t)kt * 5120 + idx * 4);
        }
        int nk = kt * 32;
#pragma unroll
        for (int r = 0; r < 16; r++) {
            int idx = t + 128 * r;
            int c = idx >> 4, q = idx & 15;
            cp_async8(sbase + (OFF_V + s * 4608 + c * 36 + 2 * q) * 4,
                      Vg + (size_t)c * 4096 + nk + 2 * q);
        }
    };

    issue(0, 0); cp_commit();
    issue(1, 1); cp_commit();

    float oacc[16][4];
#pragma unroll
    for (int nf = 0; nf < 16; nf++)
#pragma unroll
        for (int r = 0; r < 4; r++) oacc[nf][r] = 0.f;
    float m0 = -1e30f, m1 = -1e30f, l0 = 0.f, l1 = 0.f;

    const int r0 = 16 * w + g2;

    for (int kt = 0; kt < NKT; kt++) {
        cp_wait1();
        __syncthreads();
        const int s = kt & 1;
        const uint32_t* Kh = smu + OFF_K + s * 5120;
        const uint32_t* Kl = Kh + 2560;
        const uint32_t* Vt = smu + OFF_V + s * 4608;

        // ---- S = Q^T K (bf16 split, 3 MMAs per chunk) ----
        float sacc[4][4];
#pragma unroll
        for (int jf = 0; jf < 4; jf++)
#pragma unroll
            for (int r = 0; r < 4; r++) sacc[jf][r] = 0.f;

#pragma unroll
        for (int kc = 0; kc < 8; kc++) {
            const int ra = (8 * kc + tid) * 40;
            const int rb = (8 * kc + tid + 4) * 40;
#pragma unroll
            for (int jf = 0; jf < 4; jf++) {
                const int col = 8 * jf + g2;
                uint32_t bh0 = Kh[ra + col], bh1 = Kh[rb + col];
                uint32_t bl0 = Kl[ra + col], bl1 = Kl[rb + col];
                mma_bf16(sacc[jf], qh[kc], bh0, bh1);
                mma_bf16(sacc[jf], ql[kc], bh0, bh1);
                mma_bf16(sacc[jf], qh[kc], bl0, bl1);
            }
        }

        // ---- online softmax ----
        float mx0 = fmaxf(fmaxf(sacc[0][0], sacc[0][1]), fmaxf(sacc[1][0], sacc[1][1]));
        mx0 = fmaxf(mx0, fmaxf(fmaxf(sacc[2][0], sacc[2][1]), fmaxf(sacc[3][0], sacc[3][1])));
        float mx1 = fmaxf(fmaxf(sacc[0][2], sacc[0][3]), fmaxf(sacc[1][2], sacc[1][3]));
        mx1 = fmaxf(mx1, fmaxf(fmaxf(sacc[2][2], sacc[2][3]), fmaxf(sacc[3][2], sacc[3][3])));
        mx0 = fmaxf(mx0, __shfl_xor_sync(0xffffffffu, mx0, 1));
        mx0 = fmaxf(mx0, __shfl_xor_sync(0xffffffffu, mx0, 2));
        mx1 = fmaxf(mx1, __shfl_xor_sync(0xffffffffu, mx1, 1));
        mx1 = fmaxf(mx1, __shfl_xor_sync(0xffffffffu, mx1, 2));

        float mn0 = fmaxf(m0, mx0), mn1 = fmaxf(m1, mx1);
        float sc0 = __expf(m0 - mn0), sc1 = __expf(m1 - mn1);
        m0 = mn0; m1 = mn1;

        float rs0 = 0.f, rs1 = 0.f;
#pragma unroll
        for (int jf = 0; jf < 4; jf++) {
            float p00 = __expf(sacc[jf][0] - m0);
            float p01 = __expf(sacc[jf][1] - m0);
            float p10 = __expf(sacc[jf][2] - m1);
            float p11 = __expf(sacc[jf][3] - m1);
            rs0 += p00 + p01;
            rs1 += p10 + p11;
            int cbase = 8 * jf + 2 * tid;
            Ps[r0 * 36 + cbase]           = f2tf32(p00);
            Ps[r0 * 36 + cbase + 1]       = f2tf32(p01);
            Ps[(r0 + 8) * 36 + cbase]     = f2tf32(p10);
            Ps[(r0 + 8) * 36 + cbase + 1] = f2tf32(p11);
        }
        rs0 += __shfl_xor_sync(0xffffffffu, rs0, 1);
        rs0 += __shfl_xor_sync(0xffffffffu, rs0, 2);
        rs1 += __shfl_xor_sync(0xffffffffu, rs1, 1);
        rs1 += __shfl_xor_sync(0xffffffffu, rs1, 2);
        l0 = l0 * sc0 + rs0;
        l1 = l1 * sc1 + rs1;

#pragma unroll
        for (int nf = 0; nf < 16; nf++) {
            oacc[nf][0] *= sc0; oacc[nf][1] *= sc0;
            oacc[nf][2] *= sc1; oacc[nf][3] *= sc1;
        }
        __syncwarp();

        // ---- O += P V^T (tf32) ----
#pragma unroll
        for (int kc = 0; kc < 4; kc++) {
            uint32_t pa[4];
            pa[0] = Ps[r0 * 36 + 8 * kc + tid];
            pa[1] = Ps[(r0 + 8) * 36 + 8 * kc + tid];
            pa[2] = Ps[r0 * 36 + 8 * kc + tid + 4];
            pa[3] = Ps[(r0 + 8) * 36 + 8 * kc + tid + 4];
#pragma unroll
            for (int nf = 0; nf < 16; nf++) {
                uint32_t b0 = Vt[(8 * nf + g2) * 36 + 8 * kc + tid];
                uint32_t b1 = Vt[(8 * nf + g2) * 36 + 8 * kc + tid + 4];
                mma_tf32(oacc[nf], pa, b0, b1);
            }
        }

        __syncthreads();
        if (kt + 2 < NKT) issue(s, kt + 2);
        cp_commit();    // always commit (possibly empty group) to keep wait bookkeeping exact
    }

    // ---- normalize, stage O (reuse K region), residual, write ----
    float* OSf = (float*)smu;       // [128][68]
    {
        float inv0 = 1.f / l0, inv1 = 1.f / l1;
#pragma unroll
        for (int nf = 0; nf < 16; nf++) {
            int c = 8 * nf + 2 * tid;
            OSf[c * 68 + r0]           = oacc[nf][0] * inv0;
            OSf[(c + 1) * 68 + r0]     = oacc[nf][1] * inv0;
            OSf[c * 68 + r0 + 8]       = oacc[nf][2] * inv1;
            OSf[(c + 1) * 68 + r0 + 8] = oacc[nf][3] * inv1;
        }
    }
    __syncthreads();

    const float gm = gamma[0];
    const float* xB  = x    + (size_t)b * C_ * N_ + N0;
    float*       saB = g_SA + (size_t)b * C_ * N_ + N0;
    for (int v = t; v < 2048; v += 128) {
        int c = v >> 4, q = (v & 15) * 4;
        float4 o  = *(float4*)&OSf[c * 68 + q];
        float4 xv = *(const float4*)(xB + (size_t)c * N_ + q);
        float4 rr = make_float4(gm * o.x + xv.x, gm * o.y + xv.y,
                                gm * o.z + xv.z, gm * o.w + xv.w);
        *(float4*)(saB + (size_t)c * N_ + q) = rr;
    }
}

// ---------------------------------------------------------------------------
extern "C" void kernel_launch(void* const* d_in, const int* in_sizes, int n_in,
                              void* d_out, int out_size)
{
    const float* x     = (const float*)d_in[0];
    const float* Wq    = (const float*)d_in[1];
    const float* bq    = (const float*)d_in[2];
    const float* Wk    = (const float*)d_in[3];
    const float* bk    = (const float*)d_in[4];
    const float* Wv    = (const float*)d_in[5];
    const float* bv    = (const float*)d_in[6];
    const float* gamma = (const float*)d_in[7];
    const float* Wo    = (const float*)d_in[8];
    const float* bo    = (const float*)d_in[9];
    float* out = (float*)d_out;

    float* SAp;
    cudaGetSymbolAddress((void**)&SAp, g_SA);

    static bool attr_done = false;
    if (!attr_done) {
        cudaFuncSetAttribute(qkv_proj_kernel,
                             cudaFuncAttributeMaxDynamicSharedMemorySize, QKV_SMEM_BYTES);
        cudaFuncSetAttribute(attn_kernel,
                             cudaFuncAttributeMaxDynamicSharedMemorySize, ATTN_SMEM_BYTES);
        attr_done = true;
    }

    dim3 grid(N_ / 64, B_);
    qkv_proj_kernel<<<grid, 256, QKV_SMEM_BYTES>>>(x, Wq, bq, Wk, bk, Wv, bv);
    attn_kernel<<<grid, 128, ATTN_SMEM_BYTES>>>(x, gamma);
    proj_kernel<<<grid, 256>>>(SAp, Wo, bo, out);
}

// round 4
// speedup vs baseline: 3.6956x; 1.0473x over previous
#include <cuda_runtime.h>
#include <cuda_bf16.h>
#include <cstdint>

#define B_  4
#define C_  128
#define N_  4096
#define CO_ 128
#define NKT 128

// -------- scratch device globals --------
__device__ uint32_t g_Qh[B_ * 4096 * 64];     // [b][i][crow] bf16x2 hi
__device__ uint32_t g_Ql[B_ * 4096 * 64];     // lo
__device__ uint32_t g_Kf[B_ * NKT * 4096];    // [b][kt][ ((kc*4+jf)*32+lane)*4 + slot ]
__device__ uint32_t g_Vf[B_ * NKT * 4096];    // [b][kt][ ((kc*16+nf)*32+lane)*2 + half ]
__device__ float    g_SA[B_ * C_ * N_];

// -------- helpers --------
__device__ __forceinline__ uint32_t f2tf32(float x) {
    uint32_t r;
    asm("cvt.rna.tf32.f32 %0, %1;" : "=r"(r) : "f"(x));
    return r;
}
__device__ __forceinline__ void bf16_split(float x, uint16_t& h, uint16_t& l) {
    __nv_bfloat16 hb = __float2bfloat16_rn(x);
    float hf = __bfloat162float(hb);
    __nv_bfloat16 lb = __float2bfloat16_rn(x - hf);
    h = __bfloat16_as_ushort(hb);
    l = __bfloat16_as_ushort(lb);
}
__device__ __forceinline__ uint32_t pack16(uint16_t lo, uint16_t hi) {
    return (uint32_t)lo | ((uint32_t)hi << 16);
}
__device__ __forceinline__ void mma_tf32(float* c, const uint32_t* a,
                                         uint32_t b0, uint32_t b1) {
    asm volatile(
        "mma.sync.aligned.m16n8k8.row.col.f32.tf32.tf32.f32 "
        "{%0,%1,%2,%3}, {%4,%5,%6,%7}, {%8,%9}, {%0,%1,%2,%3};"
        : "+f"(c[0]), "+f"(c[1]), "+f"(c[2]), "+f"(c[3])
        : "r"(a[0]), "r"(a[1]), "r"(a[2]), "r"(a[3]), "r"(b0), "r"(b1));
}
__device__ __forceinline__ void mma_bf16(float* c, const uint32_t* a,
                                         uint32_t b0, uint32_t b1) {
    asm volatile(
        "mma.sync.aligned.m16n8k16.row.col.f32.bf16.bf16.f32 "
        "{%0,%1,%2,%3}, {%4,%5,%6,%7}, {%8,%9}, {%0,%1,%2,%3};"
        : "+f"(c[0]), "+f"(c[1]), "+f"(c[2]), "+f"(c[3])
        : "r"(a[0]), "r"(a[1]), "r"(a[2]), "r"(a[3]), "r"(b0), "r"(b1));
}
__device__ __forceinline__ void cp_async16(uint32_t dst, const void* src) {
    asm volatile("cp.async.cg.shared.global [%0], [%1], 16;" :: "r"(dst), "l"(src));
}
__device__ __forceinline__ void cp_commit() { asm volatile("cp.async.commit_group;"); }
__device__ __forceinline__ void cp_wait1()  { asm volatile("cp.async.wait_group 1;"); }

// ---------------------------------------------------------------------------
// Shared GEMM body for projections (round-1 structure: 256 thr, 4o x 8n tile)
// Computes acc[4][8] for channels o0..o0+3, positions nblk*64+n0..+7, then
// the caller-specific epilogue writes it out. EPI: 0=Q, 1=K, 2=V.
// ---------------------------------------------------------------------------
template <int EPI>
__global__ __launch_bounds__(256) void proj_pack_kernel(
    const float* __restrict__ src, const float* __restrict__ W,
    const float* __restrict__ bias)
{
    __shared__ float Wt[32][132];
    __shared__ float xs[32][64];

    const int t = threadIdx.x, nblk = blockIdx.x, b = blockIdx.y;
    const int n0 = 8 * (t & 7), o0 = 4 * (t >> 3);

    float acc[4][8];
#pragma unroll
    for (int i = 0; i < 4; i++)
#pragma unroll
        for (int j = 0; j < 8; j++) acc[i][j] = 0.f;

    const float* srcB = src + (size_t)b * C_ * N_ + (size_t)nblk * 64;

    for (int k0 = 0; k0 < C_; k0 += 32) {
        for (int v = t; v < 1024; v += 256) {
            int o = v >> 3, q = v & 7;
            float4 w = *(const float4*)(W + (size_t)o * C_ + k0 + 4 * q);
            Wt[4 * q + 0][o] = w.x;
            Wt[4 * q + 1][o] = w.y;
            Wt[4 * q + 2][o] = w.z;
            Wt[4 * q + 3][o] = w.w;
        }
        for (int v = t; v < 512; v += 256) {
            int k = v >> 4, q = (v & 15) * 4;
            *(float4*)&xs[k][q] = *(const float4*)(srcB + (size_t)(k0 + k) * N_ + q);
        }
        __syncthreads();

#pragma unroll
        for (int k = 0; k < 32; k++) {
            float4 w  = *(float4*)&Wt[k][o0];
            float4 xa = *(float4*)&xs[k][n0];
            float4 xb = *(float4*)&xs[k][n0 + 4];
            float wv[4] = {w.x, w.y, w.z, w.w};
            float xv[8] = {xa.x, xa.y, xa.z, xa.w, xb.x, xb.y, xb.z, xb.w};
#pragma unroll
            for (int i = 0; i < 4; i++)
#pragma unroll
                for (int j = 0; j < 8; j++)
                    acc[i][j] = fmaf(wv[i], xv[j], acc[i][j]);
        }
        __syncthreads();
    }

    const float b0v = bias[o0], b1v = bias[o0 + 1], b2v = bias[o0 + 2], b3v = bias[o0 + 3];

    if (EPI == 0) {
        // Q: [b][i][crow] hi/lo packed pairs of channels
        const int crow = o0 >> 1;
#pragma unroll
        for (int jj = 0; jj < 8; jj++) {
            int n = nblk * 64 + n0 + jj;
            uint16_t h0, l0, h1, l1, h2, l2, h3, l3;
            bf16_split(acc[0][jj] + b0v, h0, l0);
            bf16_split(acc[1][jj] + b1v, h1, l1);
            bf16_split(acc[2][jj] + b2v, h2, l2);
            bf16_split(acc[3][jj] + b3v, h3, l3);
            size_t qb = ((size_t)b * 4096 + n) * 64 + crow;
            g_Qh[qb]     = pack16(h0, h1);
            g_Qh[qb + 1] = pack16(h2, h3);
            g_Ql[qb]     = pack16(l0, l1);
            g_Ql[qb + 1] = pack16(l2, l3);
        }
    } else if (EPI == 1) {
        // K: frag-packed uint4 {bh0,bh1,bl0,bl1}, element slots written singly
#pragma unroll
        for (int jj = 0; jj < 8; jj++) {
            int n = nblk * 64 + n0 + jj;
            int kt = n >> 5, j = n & 31;
            int jf = j >> 3, g2 = j & 7;
            uint16_t h0, l0, h1, l1, h2, l2, h3, l3;
            bf16_split(acc[0][jj] + b0v, h0, l0);
            bf16_split(acc[1][jj] + b1v, h1, l1);
            bf16_split(acc[2][jj] + b2v, h2, l2);
            bf16_split(acc[3][jj] + b3v, h3, l3);
            uint32_t hip[2] = {pack16(h0, h1), pack16(h2, h3)};
            uint32_t lop[2] = {pack16(l0, l1), pack16(l2, l3)};
            size_t base = ((size_t)b * NKT + kt) * 4096;
#pragma unroll
            for (int p = 0; p < 2; p++) {
                int cr  = (o0 >> 1) + p;
                int kc  = cr >> 3, r8 = cr & 7;
                int tidw = r8 & 3, half = r8 >> 2;
                int lane = g2 * 4 + tidw;
                size_t e = base + (size_t)(((kc * 4 + jf) * 32 + lane)) * 4;
                g_Kf[e + half]     = hip[p];
                g_Kf[e + 2 + half] = lop[p];
            }
        }
    } else {
        // V: frag-packed tf32 uint2 {b0,b1}
#pragma unroll
        for (int i = 0; i < 4; i++) {
            int c = o0 + i;
            int nf = c >> 3, g2 = c & 7;
            float bv = bias[c];
#pragma unroll
            for (int jj = 0; jj < 8; jj++) {
                int n = nblk * 64 + n0 + jj;
                int kt = n >> 5, j = n & 31;
                int kc = j >> 3, jm = j & 7;
                int tidj = jm & 3, half = jm >> 2;
                int lane = g2 * 4 + tidj;
                size_t e = ((size_t)b * NKT + kt) * 4096 +
                           (size_t)((kc * 16 + nf) * 32 + lane) * 2 + half;
                g_Vf[e] = f2tf32(acc[i][jj] + bv);
            }
        }
    }
}

// ---------------------------------------------------------------------------
// out-proj (fp32, round-1 style)
// ---------------------------------------------------------------------------
__global__ __launch_bounds__(256) void proj_kernel(
    const float* __restrict__ src, const float* __restrict__ W,
    const float* __restrict__ bias, float* __restrict__ dst)
{
    __shared__ float Wt[32][132];
    __shared__ float xs[32][64];

    const int t = threadIdx.x, nblk = blockIdx.x, b = blockIdx.y;
    const int n0 = 8 * (t & 7), o0 = 4 * (t >> 3);

    float acc[4][8];
#pragma unroll
    for (int i = 0; i < 4; i++)
#pragma unroll
        for (int j = 0; j < 8; j++) acc[i][j] = 0.f;

    const float* srcB = src + (size_t)b * C_ * N_ + (size_t)nblk * 64;

    for (int k0 = 0; k0 < C_; k0 += 32) {
        for (int v = t; v < 1024; v += 256) {
            int o = v >> 3, q = v & 7;
            float4 w = *(const float4*)(W + (size_t)o * C_ + k0 + 4 * q);
            Wt[4 * q + 0][o] = w.x;
            Wt[4 * q + 1][o] = w.y;
            Wt[4 * q + 2][o] = w.z;
            Wt[4 * q + 3][o] = w.w;
        }
        for (int v = t; v < 512; v += 256) {
            int k = v >> 4, q = (v & 15) * 4;
            *(float4*)&xs[k][q] = *(const float4*)(srcB + (size_t)(k0 + k) * N_ + q);
        }
        __syncthreads();

#pragma unroll
        for (int k = 0; k < 32; k++) {
            float4 w  = *(float4*)&Wt[k][o0];
            float4 xa = *(float4*)&xs[k][n0];
            float4 xb = *(float4*)&xs[k][n0 + 4];
            float wv[4] = {w.x, w.y, w.z, w.w};
            float xv[8] = {xa.x, xa.y, xa.z, xa.w, xb.x, xb.y, xb.z, xb.w};
#pragma unroll
            for (int i = 0; i < 4; i++)
#pragma unroll
                for (int j = 0; j < 8; j++)
                    acc[i][j] = fmaf(wv[i], xv[j], acc[i][j]);
        }
        __syncthreads();
    }

#pragma unroll
    for (int i = 0; i < 4; i++) {
        float bv = bias[o0 + i];
        float* drow = dst + ((size_t)b * 128 + (o0 + i)) * N_ + (size_t)nblk * 64 + n0;
        *(float4*)(drow)     = make_float4(acc[i][0] + bv, acc[i][1] + bv, acc[i][2] + bv, acc[i][3] + bv);
        *(float4*)(drow + 4) = make_float4(acc[i][4] + bv, acc[i][5] + bv, acc[i][6] + bv, acc[i][7] + bv);
    }
}

// ---------------------------------------------------------------------------
// attn: bf16-split QK^T + tf32 PV, frag-packed smem, cp.async double buffer.
// Block = 128 threads (4 warps), 64-query tile, 32-key tiles.
// ---------------------------------------------------------------------------
// smem (uints)
#define OFF_K 0                     // [2][4096]
#define OFF_V 8192                  // [2][4096]
#define OFF_P 16384                 // [64][36]
#define SM_UINTS 18688
#define ATTN_SMEM_BYTES (SM_UINTS * 4)

__global__ __launch_bounds__(128) void attn_kernel(
    const float* __restrict__ x, const float* __restrict__ gamma)
{
    extern __shared__ uint32_t smu[];
    uint32_t* Ps = smu + OFF_P;

    const int t = threadIdx.x;
    const int w = t >> 5, lane = t & 31;
    const int g2 = lane >> 2, tid = lane & 3;
    const int qblk = blockIdx.x, b = blockIdx.y;
    const int N0 = qblk * 64;
    const int I0 = N0 + 16 * w;

    const uint32_t sbase = (uint32_t)__cvta_generic_to_shared(smu);

    // ---- Q A-fragments into registers ----
    uint32_t qh[8][4], ql[8][4];
    {
        const uint32_t* Qhg = g_Qh + ((size_t)b * 4096 + I0) * 64;
        const uint32_t* Qlg = g_Ql + ((size_t)b * 4096 + I0) * 64;
        const int r0c = g2 * 64, r8c = (g2 + 8) * 64;
#pragma unroll
        for (int kc = 0; kc < 8; kc++) {
            int cl = 8 * kc + tid;
            qh[kc][0] = Qhg[r0c + cl];     qh[kc][1] = Qhg[r8c + cl];
            qh[kc][2] = Qhg[r0c + cl + 4]; qh[kc][3] = Qhg[r8c + cl + 4];
            ql[kc][0] = Qlg[r0c + cl];     ql[kc][1] = Qlg[r8c + cl];
            ql[kc][2] = Qlg[r0c + cl + 4]; ql[kc][3] = Qlg[r8c + cl + 4];
        }
    }

    const uint32_t* Kg = g_Kf + (size_t)b * NKT * 4096;
    const uint32_t* Vg = g_Vf + (size_t)b * NKT * 4096;

    auto issue = [&](int s, int kt) {
#pragma unroll
        for (int r = 0; r < 8; r++) {
            int i4 = t + 128 * r;   // uint4 index 0..1023
            cp_async16(sbase + (OFF_K + s * 4096) * 4 + i4 * 16,
                       Kg + (size_t)kt * 4096 + i4 * 4);
            cp_async16(sbase + (OFF_V + s * 4096) * 4 + i4 * 16,
                       Vg + (size_t)kt * 4096 + i4 * 4);
        }
    };

    issue(0, 0); cp_commit();
    issue(1, 1); cp_commit();

    float oacc[16][4];
#pragma unroll
    for (int nf = 0; nf < 16; nf++)
#pragma unroll
        for (int r = 0; r < 4; r++) oacc[nf][r] = 0.f;
    float m0 = -1e30f, m1 = -1e30f, l0 = 0.f, l1 = 0.f;

    const int r0 = 16 * w + g2;

    for (int kt = 0; kt < NKT; kt++) {
        cp_wait1();
        __syncthreads();
        const int s = kt & 1;
        const uint32_t* Kf = smu + OFF_K + s * 4096;
        const uint32_t* Vf = smu + OFF_V + s * 4096;

        // ---- S = Q^T K (bf16 split, LDS.128 frags) ----
        float sacc[4][4];
#pragma unroll
        for (int jf = 0; jf < 4; jf++)
#pragma unroll
            for (int r = 0; r < 4; r++) sacc[jf][r] = 0.f;

#pragma unroll
        for (int kc = 0; kc < 8; kc++) {
#pragma unroll
            for (int jf = 0; jf < 4; jf++) {
                uint4 kb = *(const uint4*)&Kf[(((kc * 4 + jf) * 32) + lane) * 4];
                mma_bf16(sacc[jf], qh[kc], kb.x, kb.y);
                mma_bf16(sacc[jf], ql[kc], kb.x, kb.y);
                mma_bf16(sacc[jf], qh[kc], kb.z, kb.w);
            }
        }

        // ---- online softmax ----
        float mx0 = fmaxf(fmaxf(sacc[0][0], sacc[0][1]), fmaxf(sacc[1][0], sacc[1][1]));
        mx0 = fmaxf(mx0, fmaxf(fmaxf(sacc[2][0], sacc[2][1]), fmaxf(sacc[3][0], sacc[3][1])));
        float mx1 = fmaxf(fmaxf(sacc[0][2], sacc[0][3]), fmaxf(sacc[1][2], sacc[1][3]));
        mx1 = fmaxf(mx1, fmaxf(fmaxf(sacc[2][2], sacc[2][3]), fmaxf(sacc[3][2], sacc[3][3])));
        mx0 = fmaxf(mx0, __shfl_xor_sync(0xffffffffu, mx0, 1));
        mx0 = fmaxf(mx0, __shfl_xor_sync(0xffffffffu, mx0, 2));
        mx1 = fmaxf(mx1, __shfl_xor_sync(0xffffffffu, mx1, 1));
        mx1 = fmaxf(mx1, __shfl_xor_sync(0xffffffffu, mx1, 2));

        float mn0 = fmaxf(m0, mx0), mn1 = fmaxf(m1, mx1);
        float sc0 = __expf(m0 - mn0), sc1 = __expf(m1 - mn1);
        m0 = mn0; m1 = mn1;

        float rs0 = 0.f, rs1 = 0.f;
#pragma unroll
        for (int jf = 0; jf < 4; jf++) {
            float p00 = __expf(sacc[jf][0] - m0);
            float p01 = __expf(sacc[jf][1] - m0);
            float p10 = __expf(sacc[jf][2] - m1);
            float p11 = __expf(sacc[jf][3] - m1);
            rs0 += p00 + p01;
            rs1 += p10 + p11;
            int cbase = 8 * jf + 2 * tid;
            Ps[r0 * 36 + cbase]           = f2tf32(p00);
            Ps[r0 * 36 + cbase + 1]       = f2tf32(p01);
            Ps[(r0 + 8) * 36 + cbase]     = f2tf32(p10);
            Ps[(r0 + 8) * 36 + cbase + 1] = f2tf32(p11);
        }
        rs0 += __shfl_xor_sync(0xffffffffu, rs0, 1);
        rs0 += __shfl_xor_sync(0xffffffffu, rs0, 2);
        rs1 += __shfl_xor_sync(0xffffffffu, rs1, 1);
        rs1 += __shfl_xor_sync(0xffffffffu, rs1, 2);
        l0 = l0 * sc0 + rs0;
        l1 = l1 * sc1 + rs1;

#pragma unroll
        for (int nf = 0; nf < 16; nf++) {
            oacc[nf][0] *= sc0; oacc[nf][1] *= sc0;
            oacc[nf][2] *= sc1; oacc[nf][3] *= sc1;
        }
        __syncwarp();

        // ---- O += P V^T (tf32, LDS.64 frags) ----
#pragma unroll
        for (int kc = 0; kc < 4; kc++) {
            uint32_t pa[4];
            pa[0] = Ps[r0 * 36 + 8 * kc + tid];
            pa[1] = Ps[(r0 + 8) * 36 + 8 * kc + tid];
            pa[2] = Ps[r0 * 36 + 8 * kc + tid + 4];
            pa[3] = Ps[(r0 + 8) * 36 + 8 * kc + tid + 4];
#pragma unroll
            for (int nf = 0; nf < 16; nf++) {
                uint2 vb = *(const uint2*)&Vf[((kc * 16 + nf) * 32 + lane) * 2];
                mma_tf32(oacc[nf], pa, vb.x, vb.y);
            }
        }

        __syncthreads();
        if (kt + 2 < NKT) issue(s, kt + 2);
        cp_commit();
    }

    // ---- normalize, stage O, residual, write ----
    float* OSf = (float*)smu;       // [128][68] = 8704 floats, fits
    {
        float inv0 = 1.f / l0, inv1 = 1.f / l1;
#pragma unroll
        for (int nf = 0; nf < 16; nf++) {
            int c = 8 * nf + 2 * tid;
            OSf[c * 68 + r0]           = oacc[nf][0] * inv0;
            OSf[(c + 1) * 68 + r0]     = oacc[nf][1] * inv0;
            OSf[c * 68 + r0 + 8]       = oacc[nf][2] * inv1;
            OSf[(c + 1) * 68 + r0 + 8] = oacc[nf][3] * inv1;
        }
    }
    __syncthreads();

    const float gm = gamma[0];
    const float* xB  = x    + (size_t)b * C_ * N_ + N0;
    float*       saB = g_SA + (size_t)b * C_ * N_ + N0;
    for (int v = t; v < 2048; v += 128) {
        int c = v >> 4, q = (v & 15) * 4;
        float4 o  = *(float4*)&OSf[c * 68 + q];
        float4 xv = *(const float4*)(xB + (size_t)c * N_ + q);
        float4 rr = make_float4(gm * o.x + xv.x, gm * o.y + xv.y,
                                gm * o.z + xv.z, gm * o.w + xv.w);
        *(float4*)(saB + (size_t)c * N_ + q) = rr;
    }
}

// ---------------------------------------------------------------------------
extern "C" void kernel_launch(void* const* d_in, const int* in_sizes, int n_in,
                              void* d_out, int out_size)
{
    const float* x     = (const float*)d_in[0];
    const float* Wq    = (const float*)d_in[1];
    const float* bq    = (const float*)d_in[2];
    const float* Wk    = (const float*)d_in[3];
    const float* bk    = (const float*)d_in[4];
    const float* Wv    = (const float*)d_in[5];
    const float* bv    = (const float*)d_in[6];
    const float* gamma = (const float*)d_in[7];
    const float* Wo    = (const float*)d_in[8];
    const float* bo    = (const float*)d_in[9];
    float* out = (float*)d_out;

    float* SAp;
    cudaGetSymbolAddress((void**)&SAp, g_SA);

    cudaFuncSetAttribute(attn_kernel,
                         cudaFuncAttributeMaxDynamicSharedMemorySize, ATTN_SMEM_BYTES);

    dim3 grid(N_ / 64, B_);
    proj_pack_kernel<0><<<grid, 256>>>(x, Wq, bq);
    proj_pack_kernel<1><<<grid, 256>>>(x, Wk, bk);
    proj_pack_kernel<2><<<grid, 256>>>(x, Wv, bv);
    attn_kernel<<<grid, 128, ATTN_SMEM_BYTES>>>(x, gamma);
    proj_kernel<<<grid, 256>>>(SAp, Wo, bo, out);
}

// round 5
// speedup vs baseline: 3.7021x; 1.0018x over previous
#include <cuda_runtime.h>
#include <cuda_bf16.h>
#include <cstdint>

#define B_  4
#define C_  128
#define N_  4096
#define CO_ 128
#define NKT 128

// -------- scratch device globals --------
__device__ uint32_t g_Qh[B_ * 4096 * 64];     // [b][i][crow] bf16x2 hi
__device__ uint32_t g_Ql[B_ * 4096 * 64];     // lo
__device__ uint32_t g_Kf[B_ * NKT * 4096];    // [b][kt][ ((kc*4+jf)*32+lane)*4 + slot ]
__device__ uint32_t g_Vf[B_ * NKT * 4096];    // [b][kt][ ((kc*16+nf)*32+lane)*2 + half ]
__device__ float    g_SA[B_ * C_ * N_];

// -------- helpers --------
__device__ __forceinline__ uint32_t f2tf32(float x) {
    uint32_t r;
    asm("cvt.rna.tf32.f32 %0, %1;" : "=r"(r) : "f"(x));
    return r;
}
__device__ __forceinline__ void bf16_split(float x, uint16_t& h, uint16_t& l) {
    __nv_bfloat16 hb = __float2bfloat16_rn(x);
    float hf = __bfloat162float(hb);
    __nv_bfloat16 lb = __float2bfloat16_rn(x - hf);
    h = __bfloat16_as_ushort(hb);
    l = __bfloat16_as_ushort(lb);
}
__device__ __forceinline__ uint32_t pack16(uint16_t lo, uint16_t hi) {
    return (uint32_t)lo | ((uint32_t)hi << 16);
}
__device__ __forceinline__ void mma_tf32(float* c, const uint32_t* a,
                                         uint32_t b0, uint32_t b1) {
    asm volatile(
        "mma.sync.aligned.m16n8k8.row.col.f32.tf32.tf32.f32 "
        "{%0,%1,%2,%3}, {%4,%5,%6,%7}, {%8,%9}, {%0,%1,%2,%3};"
        : "+f"(c[0]), "+f"(c[1]), "+f"(c[2]), "+f"(c[3])
        : "r"(a[0]), "r"(a[1]), "r"(a[2]), "r"(a[3]), "r"(b0), "r"(b1));
}
__device__ __forceinline__ void mma_bf16(float* c, const uint32_t* a,
                                         uint32_t b0, uint32_t b1) {
    asm volatile(
        "mma.sync.aligned.m16n8k16.row.col.f32.bf16.bf16.f32 "
        "{%0,%1,%2,%3}, {%4,%5,%6,%7}, {%8,%9}, {%0,%1,%2,%3};"
        : "+f"(c[0]), "+f"(c[1]), "+f"(c[2]), "+f"(c[3])
        : "r"(a[0]), "r"(a[1]), "r"(a[2]), "r"(a[3]), "r"(b0), "r"(b1));
}
__device__ __forceinline__ void cp_async16(uint32_t dst, const void* src) {
    asm volatile("cp.async.cg.shared.global [%0], [%1], 16;" :: "r"(dst), "l"(src));
}
__device__ __forceinline__ void cp_commit() { asm volatile("cp.async.commit_group;"); }
__device__ __forceinline__ void cp_wait1()  { asm volatile("cp.async.wait_group 1;"); }

// ---------------------------------------------------------------------------
// Shared GEMM body for projections (round-1 structure: 256 thr, 4o x 8n tile)
// Computes acc[4][8] for channels o0..o0+3, positions nblk*64+n0..+7, then
// the caller-specific epilogue writes it out. EPI: 0=Q, 1=K, 2=V.
// ---------------------------------------------------------------------------
template <int EPI>
__global__ __launch_bounds__(256) void proj_pack_kernel(
    const float* __restrict__ src, const float* __restrict__ W,
    const float* __restrict__ bias)
{
    __shared__ float Wt[32][132];
    __shared__ float xs[32][64];

    const int t = threadIdx.x, nblk = blockIdx.x, b = blockIdx.y;
    const int n0 = 8 * (t & 7), o0 = 4 * (t >> 3);

    float acc[4][8];
#pragma unroll
    for (int i = 0; i < 4; i++)
#pragma unroll
        for (int j = 0; j < 8; j++) acc[i][j] = 0.f;

    const float* srcB = src + (size_t)b * C_ * N_ + (size_t)nblk * 64;

    for (int k0 = 0; k0 < C_; k0 += 32) {
        for (int v = t; v < 1024; v += 256) {
            int o = v >> 3, q = v & 7;
            float4 w = *(const float4*)(W + (size_t)o * C_ + k0 + 4 * q);
            Wt[4 * q + 0][o] = w.x;
            Wt[4 * q + 1][o] = w.y;
            Wt[4 * q + 2][o] = w.z;
            Wt[4 * q + 3][o] = w.w;
        }
        for (int v = t; v < 512; v += 256) {
            int k = v >> 4, q = (v & 15) * 4;
            *(float4*)&xs[k][q] = *(const float4*)(srcB + (size_t)(k0 + k) * N_ + q);
        }
        __syncthreads();

#pragma unroll
        for (int k = 0; k < 32; k++) {
            float4 w  = *(float4*)&Wt[k][o0];
            float4 xa = *(float4*)&xs[k][n0];
            float4 xb = *(float4*)&xs[k][n0 + 4];
            float wv[4] = {w.x, w.y, w.z, w.w};
            float xv[8] = {xa.x, xa.y, xa.z, xa.w, xb.x, xb.y, xb.z, xb.w};
#pragma unroll
            for (int i = 0; i < 4; i++)
#pragma unroll
                for (int j = 0; j < 8; j++)
                    acc[i][j] = fmaf(wv[i], xv[j], acc[i][j]);
        }
        __syncthreads();
    }

    const float b0v = bias[o0], b1v = bias[o0 + 1], b2v = bias[o0 + 2], b3v = bias[o0 + 3];

    if (EPI == 0) {
        // Q: [b][i][crow] hi/lo packed pairs of channels
        const int crow = o0 >> 1;
#pragma unroll
        for (int jj = 0; jj < 8; jj++) {
            int n = nblk * 64 + n0 + jj;
            uint16_t h0, l0, h1, l1, h2, l2, h3, l3;
            bf16_split(acc[0][jj] + b0v, h0, l0);
            bf16_split(acc[1][jj] + b1v, h1, l1);
            bf16_split(acc[2][jj] + b2v, h2, l2);
            bf16_split(acc[3][jj] + b3v, h3, l3);
            size_t qb = ((size_t)b * 4096 + n) * 64 + crow;
            g_Qh[qb]     = pack16(h0, h1);
            g_Qh[qb + 1] = pack16(h2, h3);
            g_Ql[qb]     = pack16(l0, l1);
            g_Ql[qb + 1] = pack16(l2, l3);
        }
    } else if (EPI == 1) {
        // K: frag-packed uint4 {bh0,bh1,bl0,bl1}, element slots written singly
#pragma unroll
        for (int jj = 0; jj < 8; jj++) {
            int n = nblk * 64 + n0 + jj;
            int kt = n >> 5, j = n & 31;
            int jf = j >> 3, g2 = j & 7;
            uint16_t h0, l0, h1, l1, h2, l2, h3, l3;
            bf16_split(acc[0][jj] + b0v, h0, l0);
            bf16_split(acc[1][jj] + b1v, h1, l1);
            bf16_split(acc[2][jj] + b2v, h2, l2);
            bf16_split(acc[3][jj] + b3v, h3, l3);
            uint32_t hip[2] = {pack16(h0, h1), pack16(h2, h3)};
            uint32_t lop[2] = {pack16(l0, l1), pack16(l2, l3)};
            size_t base = ((size_t)b * NKT + kt) * 4096;
#pragma unroll
            for (int p = 0; p < 2; p++) {
                int cr  = (o0 >> 1) + p;
                int kc  = cr >> 3, r8 = cr & 7;
                int tidw = r8 & 3, half = r8 >> 2;
                int lane = g2 * 4 + tidw;
                size_t e = base + (size_t)(((kc * 4 + jf) * 32 + lane)) * 4;
                g_Kf[e + half]     = hip[p];
                g_Kf[e + 2 + half] = lop[p];
            }
        }
    } else {
        // V: frag-packed tf32 uint2 {b0,b1}
#pragma unroll
        for (int i = 0; i < 4; i++) {
            int c = o0 + i;
            int nf = c >> 3, g2 = c & 7;
            float bv = bias[c];
#pragma unroll
            for (int jj = 0; jj < 8; jj++) {
                int n = nblk * 64 + n0 + jj;
                int kt = n >> 5, j = n & 31;
                int kc = j >> 3, jm = j & 7;
                int tidj = jm & 3, half = jm >> 2;
                int lane = g2 * 4 + tidj;
                size_t e = ((size_t)b * NKT + kt) * 4096 +
                           (size_t)((kc * 16 + nf) * 32 + lane) * 2 + half;
                g_Vf[e] = f2tf32(acc[i][jj] + bv);
            }
        }
    }
}

// ---------------------------------------------------------------------------
// out-proj (fp32, round-1 style)
// ---------------------------------------------------------------------------
__global__ __launch_bounds__(256) void proj_kernel(
    const float* __restrict__ src, const float* __restrict__ W,
    const float* __restrict__ bias, float* __restrict__ dst)
{
    __shared__ float Wt[32][132];
    __shared__ float xs[32][64];

    const int t = threadIdx.x, nblk = blockIdx.x, b = blockIdx.y;
    const int n0 = 8 * (t & 7), o0 = 4 * (t >> 3);

    float acc[4][8];
#pragma unroll
    for (int i = 0; i < 4; i++)
#pragma unroll
        for (int j = 0; j < 8; j++) acc[i][j] = 0.f;

    const float* srcB = src + (size_t)b * C_ * N_ + (size_t)nblk * 64;

    for (int k0 = 0; k0 < C_; k0 += 32) {
        for (int v = t; v < 1024; v += 256) {
            int o = v >> 3, q = v & 7;
            float4 w = *(const float4*)(W + (size_t)o * C_ + k0 + 4 * q);
            Wt[4 * q + 0][o] = w.x;
            Wt[4 * q + 1][o] = w.y;
            Wt[4 * q + 2][o] = w.z;
            Wt[4 * q + 3][o] = w.w;
        }
        for (int v = t; v < 512; v += 256) {
            int k = v >> 4, q = (v & 15) * 4;
            *(float4*)&xs[k][q] = *(const float4*)(srcB + (size_t)(k0 + k) * N_ + q);
        }
        __syncthreads();

#pragma unroll
        for (int k = 0; k < 32; k++) {
            float4 w  = *(float4*)&Wt[k][o0];
            float4 xa = *(float4*)&xs[k][n0];
            float4 xb = *(float4*)&xs[k][n0 + 4];
            float wv[4] = {w.x, w.y, w.z, w.w};
            float xv[8] = {xa.x, xa.y, xa.z, xa.w, xb.x, xb.y, xb.z, xb.w};
#pragma unroll
            for (int i = 0; i < 4; i++)
#pragma unroll
                for (int j = 0; j < 8; j++)
                    acc[i][j] = fmaf(wv[i], xv[j], acc[i][j]);
        }
        __syncthreads();
    }

#pragma unroll
    for (int i = 0; i < 4; i++) {
        float bv = bias[o0 + i];
        float* drow = dst + ((size_t)b * 128 + (o0 + i)) * N_ + (size_t)nblk * 64 + n0;
        *(float4*)(drow)     = make_float4(acc[i][0] + bv, acc[i][1] + bv, acc[i][2] + bv, acc[i][3] + bv);
        *(float4*)(drow + 4) = make_float4(acc[i][4] + bv, acc[i][5] + bv, acc[i][6] + bv, acc[i][7] + bv);
    }
}

// ---------------------------------------------------------------------------
// attn: bf16-split QK^T + tf32 PV, frag-packed smem, cp.async double buffer.
// Block = 128 threads (4 warps), 64-query tile, 32-key tiles.
// ---------------------------------------------------------------------------
// smem (uints)
#define OFF_K 0                     // [2][4096]
#define OFF_V 8192                  // [2][4096]
#define OFF_P 16384                 // [64][36]
#define SM_UINTS 18688
#define ATTN_SMEM_BYTES (SM_UINTS * 4)

__global__ __launch_bounds__(128) void attn_kernel(
    const float* __restrict__ x, const float* __restrict__ gamma)
{
    extern __shared__ uint32_t smu[];
    uint32_t* Ps = smu + OFF_P;

    const int t = threadIdx.x;
    const int w = t >> 5, lane = t & 31;
    const int g2 = lane >> 2, tid = lane & 3;
    const int qblk = blockIdx.x, b = blockIdx.y;
    const int N0 = qblk * 64;
    const int I0 = N0 + 16 * w;

    const uint32_t sbase = (uint32_t)__cvta_generic_to_shared(smu);

    // ---- Q A-fragments into registers ----
    uint32_t qh[8][4], ql[8][4];
    {
        const uint32_t* Qhg = g_Qh + ((size_t)b * 4096 + I0) * 64;
        const uint32_t* Qlg = g_Ql + ((size_t)b * 4096 + I0) * 64;
        const int r0c = g2 * 64, r8c = (g2 + 8) * 64;
#pragma unroll
        for (int kc = 0; kc < 8; kc++) {
            int cl = 8 * kc + tid;
            qh[kc][0] = Qhg[r0c + cl];     qh[kc][1] = Qhg[r8c + cl];
            qh[kc][2] = Qhg[r0c + cl + 4]; qh[kc][3] = Qhg[r8c + cl + 4];
            ql[kc][0] = Qlg[r0c + cl];     ql[kc][1] = Qlg[r8c + cl];
            ql[kc][2] = Qlg[r0c + cl + 4]; ql[kc][3] = Qlg[r8c + cl + 4];
        }
    }

    const uint32_t* Kg = g_Kf + (size_t)b * NKT * 4096;
    const uint32_t* Vg = g_Vf + (size_t)b * NKT * 4096;

    auto issue = [&](int s, int kt) {
#pragma unroll
        for (int r = 0; r < 8; r++) {
            int i4 = t + 128 * r;   // uint4 index 0..1023
            cp_async16(sbase + (OFF_K + s * 4096) * 4 + i4 * 16,
                       Kg + (size_t)kt * 4096 + i4 * 4);
            cp_async16(sbase + (OFF_V + s * 4096) * 4 + i4 * 16,
                       Vg + (size_t)kt * 4096 + i4 * 4);
        }
    };

    issue(0, 0); cp_commit();
    issue(1, 1); cp_commit();

    float oacc[16][4];
#pragma unroll
    for (int nf = 0; nf < 16; nf++)
#pragma unroll
        for (int r = 0; r < 4; r++) oacc[nf][r] = 0.f;
    float m0 = -1e30f, m1 = -1e30f, l0 = 0.f, l1 = 0.f;

    const int r0 = 16 * w + g2;

    for (int kt = 0; kt < NKT; kt++) {
        cp_wait1();
        __syncthreads();
        const int s = kt & 1;
        const uint32_t* Kf = smu + OFF_K + s * 4096;
        const uint32_t* Vf = smu + OFF_V + s * 4096;

        // ---- S = Q^T K (bf16 split, LDS.128 frags) ----
        float sacc[4][4];
#pragma unroll
        for (int jf = 0; jf < 4; jf++)
#pragma unroll
            for (int r = 0; r < 4; r++) sacc[jf][r] = 0.f;

#pragma unroll
        for (int kc = 0; kc < 8; kc++) {
#pragma unroll
            for (int jf = 0; jf < 4; jf++) {
                uint4 kb = *(const uint4*)&Kf[(((kc * 4 + jf) * 32) + lane) * 4];
                mma_bf16(sacc[jf], qh[kc], kb.x, kb.y);
                mma_bf16(sacc[jf], ql[kc], kb.x, kb.y);
                mma_bf16(sacc[jf], qh[kc], kb.z, kb.w);
            }
        }

        // ---- online softmax ----
        float mx0 = fmaxf(fmaxf(sacc[0][0], sacc[0][1]), fmaxf(sacc[1][0], sacc[1][1]));
        mx0 = fmaxf(mx0, fmaxf(fmaxf(sacc[2][0], sacc[2][1]), fmaxf(sacc[3][0], sacc[3][1])));
        float mx1 = fmaxf(fmaxf(sacc[0][2], sacc[0][3]), fmaxf(sacc[1][2], sacc[1][3]));
        mx1 = fmaxf(mx1, fmaxf(fmaxf(sacc[2][2], sacc[2][3]), fmaxf(sacc[3][2], sacc[3][3])));
        mx0 = fmaxf(mx0, __shfl_xor_sync(0xffffffffu, mx0, 1));
        mx0 = fmaxf(mx0, __shfl_xor_sync(0xffffffffu, mx0, 2));
        mx1 = fmaxf(mx1, __shfl_xor_sync(0xffffffffu, mx1, 1));
        mx1 = fmaxf(mx1, __shfl_xor_sync(0xffffffffu, mx1, 2));

        float mn0 = fmaxf(m0, mx0), mn1 = fmaxf(m1, mx1);
        float sc0 = __expf(m0 - mn0), sc1 = __expf(m1 - mn1);
        m0 = mn0; m1 = mn1;

        float rs0 = 0.f, rs1 = 0.f;
#pragma unroll
        for (int jf = 0; jf < 4; jf++) {
            float p00 = __expf(sacc[jf][0] - m0);
            float p01 = __expf(sacc[jf][1] - m0);
            float p10 = __expf(sacc[jf][2] - m1);
            float p11 = __expf(sacc[jf][3] - m1);
            rs0 += p00 + p01;
            rs1 += p10 + p11;
            int cbase = 8 * jf + 2 * tid;
            Ps[r0 * 36 + cbase]           = f2tf32(p00);
            Ps[r0 * 36 + cbase + 1]       = f2tf32(p01);
            Ps[(r0 + 8) * 36 + cbase]     = f2tf32(p10);
            Ps[(r0 + 8) * 36 + cbase + 1] = f2tf32(p11);
        }
        rs0 += __shfl_xor_sync(0xffffffffu, rs0, 1);
        rs0 += __shfl_xor_sync(0xffffffffu, rs0, 2);
        rs1 += __shfl_xor_sync(0xffffffffu, rs1, 1);
        rs1 += __shfl_xor_sync(0xffffffffu, rs1, 2);
        l0 = l0 * sc0 + rs0;
        l1 = l1 * sc1 + rs1;

#pragma unroll
        for (int nf = 0; nf < 16; nf++) {
            oacc[nf][0] *= sc0; oacc[nf][1] *= sc0;
            oacc[nf][2] *= sc1; oacc[nf][3] *= sc1;
        }
        __syncwarp();

        // ---- O += P V^T (tf32, LDS.64 frags) ----
#pragma unroll
        for (int kc = 0; kc < 4; kc++) {
            uint32_t pa[4];
            pa[0] = Ps[r0 * 36 + 8 * kc + tid];
            pa[1] = Ps[(r0 + 8) * 36 + 8 * kc + tid];
            pa[2] = Ps[r0 * 36 + 8 * kc + tid + 4];
            pa[3] = Ps[(r0 + 8) * 36 + 8 * kc + tid + 4];
#pragma unroll
            for (int nf = 0; nf < 16; nf++) {
                uint2 vb = *(const uint2*)&Vf[((kc * 16 + nf) * 32 + lane) * 2];
                mma_tf32(oacc[nf], pa, vb.x, vb.y);
            }
        }

        __syncthreads();
        if (kt + 2 < NKT) issue(s, kt + 2);
        cp_commit();
    }

    // ---- normalize, stage O, residual, write ----
    float* OSf = (float*)smu;       // [128][68] = 8704 floats, fits
    {
        float inv0 = 1.f / l0, inv1 = 1.f / l1;
#pragma unroll
        for (int nf = 0; nf < 16; nf++) {
            int c = 8 * nf + 2 * tid;
            OSf[c * 68 + r0]           = oacc[nf][0] * inv0;
            OSf[(c + 1) * 68 + r0]     = oacc[nf][1] * inv0;
            OSf[c * 68 + r0 + 8]       = oacc[nf][2] * inv1;
            OSf[(c + 1) * 68 + r0 + 8] = oacc[nf][3] * inv1;
        }
    }
    __syncthreads();

    const float gm = gamma[0];
    const float* xB  = x    + (size_t)b * C_ * N_ + N0;
    float*       saB = g_SA + (size_t)b * C_ * N_ + N0;
    for (int v = t; v < 2048; v += 128) {
        int c = v >> 4, q = (v & 15) * 4;
        float4 o  = *(float4*)&OSf[c * 68 + q];
        float4 xv = *(const float4*)(xB + (size_t)c * N_ + q);
        float4 rr = make_float4(gm * o.x + xv.x, gm * o.y + xv.y,
                                gm * o.z + xv.z, gm * o.w + xv.w);
        *(float4*)(saB + (size_t)c * N_ + q) = rr;
    }
}

// ---------------------------------------------------------------------------
extern "C" void kernel_launch(void* const* d_in, const int* in_sizes, int n_in,
                              void* d_out, int out_size)
{
    const float* x     = (const float*)d_in[0];
    const float* Wq    = (const float*)d_in[1];
    const float* bq    = (const float*)d_in[2];
    const float* Wk    = (const float*)d_in[3];
    const float* bk    = (const float*)d_in[4];
    const float* Wv    = (const float*)d_in[5];
    const float* bv    = (const float*)d_in[6];
    const float* gamma = (const float*)d_in[7];
    const float* Wo    = (const float*)d_in[8];
    const float* bo    = (const float*)d_in[9];
    float* out = (float*)d_out;

    float* SAp;
    cudaGetSymbolAddress((void**)&SAp, g_SA);

    cudaFuncSetAttribute(attn_kernel,
                         cudaFuncAttributeMaxDynamicSharedMemorySize, ATTN_SMEM_BYTES);

    dim3 grid(N_ / 64, B_);
    proj_pack_kernel<0><<<grid, 256>>>(x, Wq, bq);
    proj_pack_kernel<1><<<grid, 256>>>(x, Wk, bk);
    proj_pack_kernel<2><<<grid, 256>>>(x, Wv, bv);
    attn_kernel<<<grid, 128, ATTN_SMEM_BYTES>>>(x, gamma);
    proj_kernel<<<grid, 256>>>(SAp, Wo, bo, out);
}